// round 11
// baseline (speedup 1.0000x reference)
#include <cuda_runtime.h>
#include <cstdint>

#define BB 32
#define SS 2048
#define DDIM 64
#define TQ 128
#define TK 64
#define NKT 32
#define NTH 256

// fp16 tile row stride: 72 elems = 144 bytes (16B-aligned, ldmatrix conflict-free)
#define RS 144
// smem byte offsets
#define OQHI 0u               // Q tile: 128 x 64 fp16 (18432 B)
#define OKHI 18432u           // K tile: 64 x 64 fp16 (9216 B)
#define OVHI 27648u           // V tile: 64 x 64 fp16 (9216 B)
#define ORAWK 36864u          // raw f32 K stage (16 KB)
#define ORAWV 53248u          // raw f32 V stage (16 KB)
#define SMEMSZ 69632u
// after-loop: linv[128] reuses the (dead) Q region
#define OLINV 0u

// ---------------- helpers ----------------
__device__ __forceinline__ uint32_t s2u(const void* p) {
    uint32_t a;
    asm("{ .reg .u64 t; cvta.to.shared.u64 t, %1; cvt.u32.u64 %0, t; }" : "=r"(a) : "l"(p));
    return a;
}
// pack (a,b) -> fp16x2 (a in low half)
__device__ __forceinline__ void packh2(float a, float b, uint32_t& h) {
    asm("cvt.rn.f16x2.f32 %0, %1, %2;" : "=r"(h) : "f"(b), "f"(a));
}
__device__ __forceinline__ void ldm4(uint32_t& r0, uint32_t& r1, uint32_t& r2, uint32_t& r3, uint32_t a) {
    asm volatile("ldmatrix.sync.aligned.m8n8.x4.shared.b16 {%0,%1,%2,%3}, [%4];"
                 : "=r"(r0), "=r"(r1), "=r"(r2), "=r"(r3) : "r"(a));
}
__device__ __forceinline__ void ldm4t(uint32_t& r0, uint32_t& r1, uint32_t& r2, uint32_t& r3, uint32_t a) {
    asm volatile("ldmatrix.sync.aligned.m8n8.x4.trans.shared.b16 {%0,%1,%2,%3}, [%4];"
                 : "=r"(r0), "=r"(r1), "=r"(r2), "=r"(r3) : "r"(a));
}
__device__ __forceinline__ void mma16816(float* c, const uint32_t* a, uint32_t b0, uint32_t b1) {
    asm volatile(
        "mma.sync.aligned.m16n8k16.row.col.f32.f16.f16.f32 "
        "{%0,%1,%2,%3}, {%4,%5,%6,%7}, {%8,%9}, {%0,%1,%2,%3};"
        : "+f"(c[0]), "+f"(c[1]), "+f"(c[2]), "+f"(c[3])
        : "r"(a[0]), "r"(a[1]), "r"(a[2]), "r"(a[3]), "r"(b0), "r"(b1));
}
__device__ __forceinline__ void cpa16(uint32_t dst, const float* src) {
    asm volatile("cp.async.cg.shared.global [%0], [%1], 16;" :: "r"(dst), "l"(src));
}
#define CPA_COMMIT() asm volatile("cp.async.commit_group;" ::: "memory")
#define CPA_WAIT0()  asm volatile("cp.async.wait_group 0;" ::: "memory")

// ---------------- main attention kernel ----------------
__global__ void __launch_bounds__(NTH, 2)
attn_mma_kernel(const float* __restrict__ q, const float* __restrict__ k,
                const float* __restrict__ v, float* __restrict__ out,
                float* __restrict__ attn)
{
    extern __shared__ char smem[];
    const uint32_t sb = s2u(smem);
    const int tid = threadIdx.x;
    const int w = tid >> 5, lane = tid & 31;
    const int quad = lane >> 2, qlane = lane & 3;
    const int qt = blockIdx.x, b = blockIdx.y;
    const int qbase = qt * TQ;

    // ---- load Q tile (128 x 64) -> fp16 smem ----
    {
        const float* qg = q + ((size_t)(b * SS + qbase)) * DDIM;
        #pragma unroll
        for (int it = 0; it < 8; ++it) {
            int idx = tid + it * NTH;           // 0..2047 float4s
            int row = idx >> 4, d4 = (idx & 15) << 2;
            float4 qv = *(const float4*)(qg + row * DDIM + d4);
            uint32_t h01, h23;
            packh2(qv.x, qv.y, h01);
            packh2(qv.z, qv.w, h23);
            *(uint2*)(smem + OQHI + row * RS + d4 * 2) = make_uint2(h01, h23);
        }
    }

    // ---- prefetch raw K/V tile 0 via cp.async ----
    {
        const float* kg = k + ((size_t)(b * SS)) * DDIM;
        const float* vg = v + ((size_t)(b * SS)) * DDIM;
        #pragma unroll
        for (int it = 0; it < 4; ++it) {
            int idx = tid + it * NTH;
            cpa16(sb + ORAWK + idx * 16, kg + idx * 4);
            cpa16(sb + ORAWV + idx * 16, vg + idx * 4);
        }
        CPA_COMMIT();
    }
    __syncthreads();

    float O[8][4];
    #pragma unroll
    for (int j = 0; j < 8; ++j)
        #pragma unroll
        for (int i = 0; i < 4; ++i) O[j][i] = 0.f;
    float lsum0 = 0.f, lsum1 = 0.f;
    const float CEXP = 0.18033688011112042f;  // (1/8)*log2(e)

    // lane base addresses
    const uint32_t qrow = (uint32_t)(w * 16 + (lane & 15)) * RS + (uint32_t)(lane >> 4) * 16;
    const uint32_t kaddr = sb + OKHI + (uint32_t)(((lane >> 4) << 3) + (lane & 7)) * RS
                         + (uint32_t)((lane >> 3) & 1) * 16;
    const uint32_t vaddr = sb + OVHI + (uint32_t)((((lane >> 3) & 1) << 3) + (lane & 7)) * RS
                         + (uint32_t)(lane >> 4) * 16;

    float* arow0 = attn + ((size_t)(b * SS + qbase + w * 16 + quad)) * SS + 2 * qlane;
    float* arow1 = arow0 + 8 * (size_t)SS;

    for (int kt = 0; kt < NKT; ++kt) {
        const int kbase = kt * TK;
        CPA_WAIT0();
        __syncthreads();   // raw(kt) visible to all; PV reads of kt-1 done

        // ---- convert raw smem f32 -> fp16 tiles (serves all 128 rows) ----
        #pragma unroll
        for (int it = 0; it < 4; ++it) {
            int idx = tid + it * NTH;
            int row = idx >> 4, d4 = (idx & 15) << 2;
            float4 kv = *(const float4*)(smem + ORAWK + idx * 16);
            uint32_t h01, h23;
            packh2(kv.x, kv.y, h01);
            packh2(kv.z, kv.w, h23);
            *(uint2*)(smem + OKHI + row * RS + d4 * 2) = make_uint2(h01, h23);
            float4 vv = *(const float4*)(smem + ORAWV + idx * 16);
            packh2(vv.x, vv.y, h01);
            packh2(vv.z, vv.w, h23);
            *(uint2*)(smem + OVHI + row * RS + d4 * 2) = make_uint2(h01, h23);
        }
        __syncthreads();

        // ---- prefetch next tile's raw K/V (overlaps with MMA phase) ----
        if (kt + 1 < NKT) {
            const float* kg = k + ((size_t)(b * SS + kbase + TK)) * DDIM;
            const float* vg = v + ((size_t)(b * SS + kbase + TK)) * DDIM;
            #pragma unroll
            for (int it = 0; it < 4; ++it) {
                int idx = tid + it * NTH;
                cpa16(sb + ORAWK + idx * 16, kg + idx * 4);
                cpa16(sb + ORAWV + idx * 16, vg + idx * 4);
            }
            CPA_COMMIT();
        }

        // ---- S = QK^T : warp = 16 rows x 64 keys ----
        float c[8][4];
        #pragma unroll
        for (int j = 0; j < 8; ++j)
            #pragma unroll
            for (int i = 0; i < 4; ++i) c[j][i] = 0.f;

        #pragma unroll
        for (int ks = 0; ks < 4; ++ks) {
            uint32_t qf0, qf1, qf2, qf3;
            ldm4(qf0, qf1, qf2, qf3, sb + OQHI + qrow + ks * 32);
            uint32_t qf[4] = { qf0, qf1, qf2, qf3 };
            #pragma unroll
            for (int ng = 0; ng < 4; ++ng) {
                uint32_t b0, b1, b2, b3;
                ldm4(b0, b1, b2, b3, kaddr + (uint32_t)ng * (16 * RS) + ks * 32);
                mma16816(c[2 * ng],     qf, b0, b1);
                mma16816(c[2 * ng + 1], qf, b2, b3);
            }
        }

        // ---- exp (overwrite c with e), attn STG (unnormalized), row sums ----
        #pragma unroll
        for (int j = 0; j < 8; ++j) {
            #pragma unroll
            for (int i = 0; i < 4; ++i) c[j][i] = exp2f(c[j][i] * CEXP);
            lsum0 += c[j][0] + c[j][1];
            lsum1 += c[j][2] + c[j][3];
            *(float2*)(arow0 + kbase + 8 * j) = make_float2(c[j][0], c[j][1]);
            *(float2*)(arow1 + kbase + 8 * j) = make_float2(c[j][2], c[j][3]);
        }

        // ---- O += P V : 4 k-steps of 16 keys ----
        #pragma unroll
        for (int ks2 = 0; ks2 < 4; ++ks2) {
            int t2 = 2 * ks2;
            uint32_t ah[4];
            packh2(c[t2][0],     c[t2][1],     ah[0]);
            packh2(c[t2][2],     c[t2][3],     ah[1]);
            packh2(c[t2 + 1][0], c[t2 + 1][1], ah[2]);
            packh2(c[t2 + 1][2], c[t2 + 1][3], ah[3]);
            uint32_t va = vaddr + (uint32_t)ks2 * (16 * RS);
            #pragma unroll
            for (int m = 0; m < 4; ++m) {
                uint32_t bh0, bh1, bh2, bh3;
                ldm4t(bh0, bh1, bh2, bh3, va + m * 32);
                mma16816(O[2 * m],     ah, bh0, bh1);
                mma16816(O[2 * m + 1], ah, bh2, bh3);
            }
        }
    }

    // ---- row sums: quad-local reduce (warp owns all keys of its rows) ----
    lsum0 += __shfl_xor_sync(0xFFFFFFFFu, lsum0, 1);
    lsum0 += __shfl_xor_sync(0xFFFFFFFFu, lsum0, 2);
    lsum1 += __shfl_xor_sync(0xFFFFFFFFu, lsum1, 1);
    lsum1 += __shfl_xor_sync(0xFFFFFFFFu, lsum1, 2);
    float inv0 = 1.0f / lsum0;
    float inv1 = 1.0f / lsum1;

    __syncthreads();   // all warps done with Q region before linv overwrites it
    float* linv = (float*)(smem + OLINV);
    if (qlane == 0) {
        linv[w * 16 + quad]     = inv0;
        linv[w * 16 + quad + 8] = inv1;
    }

    // ---- O store: direct, normalized (no cross-warp reduce needed) ----
    {
        int r0 = w * 16 + quad, r1 = r0 + 8;
        float* op0 = out + ((size_t)(b * SS + qbase + r0)) * DDIM + 2 * qlane;
        float* op1 = out + ((size_t)(b * SS + qbase + r1)) * DDIM + 2 * qlane;
        #pragma unroll
        for (int j = 0; j < 8; ++j) {
            *(float2*)(op0 + 8 * j) = make_float2(O[j][0] * inv0, O[j][1] * inv0);
            *(float2*)(op1 + 8 * j) = make_float2(O[j][2] * inv1, O[j][3] * inv1);
        }
    }
    __syncthreads();   // linv visible to all

    // ---- fused attn normalize tail (read-once/write-once hints) ----
    {
        float4* abase = (float4*)(attn + ((size_t)(b * SS + qbase)) * SS);
        #pragma unroll 8
        for (int it = 0; it < 256; ++it) {
            int idx = tid + it * NTH;       // 0..65535 float4s
            int row = idx >> 9;             // 512 float4 per row
            int c4  = idx & 511;
            float inv = linv[row];
            float4* p = abase + (size_t)row * (SS / 4) + c4;
            float4 vv = __ldcs(p);
            vv.x *= inv; vv.y *= inv; vv.z *= inv; vv.w *= inv;
            __stcs(p, vv);
        }
    }
}

extern "C" void kernel_launch(void* const* d_in, const int* in_sizes, int n_in,
                              void* d_out, int out_size)
{
    const float* q = (const float*)d_in[0];
    const float* k = (const float*)d_in[1];
    const float* v = (const float*)d_in[2];
    float* out  = (float*)d_out;
    float* attn = out + (size_t)BB * SS * DDIM;

    cudaFuncSetAttribute(attn_mma_kernel,
                         cudaFuncAttributeMaxDynamicSharedMemorySize, SMEMSZ);

    dim3 grid(SS / TQ, BB);
    attn_mma_kernel<<<grid, NTH, SMEMSZ>>>(q, k, v, out, attn);
}

// round 14
// speedup vs baseline: 1.2331x; 1.2331x over previous
#include <cuda_runtime.h>
#include <cstdint>

#define BB 32
#define SS 2048
#define DDIM 64
#define TQ 64
#define TK 64
#define NKT 32
#define NTH 256

// fp16 tile row stride: 72 elems = 144 bytes (16B-aligned, ldmatrix conflict-free)
#define RS 144
// smem byte offsets (double-buffered fp16 K/V)
#define OQHI 0u               // Q tile: 64 x 64 fp16 (9216 B)
#define OK0  9216u
#define OV0  18432u
#define OK1  27648u
#define OV1  36864u
#define BUFSZ 18432u
#define SMEMSZ 46080u
// epilogue reduce area reuses Q/K regions (dead after main loop)
#define ORED  0u        // fp32 [64][68] O partials
#define OLBUF 17408u    // fp32 [128] row-sum partials
#define OLINV 17920u    // fp32 [64] inverse row sums

// fp16 K/V scratch (8 MB each) — static device globals, no allocation
__device__ uint32_t g_kh[BB * SS * DDIM / 2];
__device__ uint32_t g_vh[BB * SS * DDIM / 2];

// ---------------- helpers ----------------
__device__ __forceinline__ uint32_t s2u(const void* p) {
    uint32_t a;
    asm("{ .reg .u64 t; cvta.to.shared.u64 t, %1; cvt.u32.u64 %0, t; }" : "=r"(a) : "l"(p));
    return a;
}
// pack (a,b) -> fp16x2 (a in low half)
__device__ __forceinline__ void packh2(float a, float b, uint32_t& h) {
    asm("cvt.rn.f16x2.f32 %0, %1, %2;" : "=r"(h) : "f"(b), "f"(a));
}
__device__ __forceinline__ void ldm4(uint32_t& r0, uint32_t& r1, uint32_t& r2, uint32_t& r3, uint32_t a) {
    asm volatile("ldmatrix.sync.aligned.m8n8.x4.shared.b16 {%0,%1,%2,%3}, [%4];"
                 : "=r"(r0), "=r"(r1), "=r"(r2), "=r"(r3) : "r"(a));
}
__device__ __forceinline__ void ldm4t(uint32_t& r0, uint32_t& r1, uint32_t& r2, uint32_t& r3, uint32_t a) {
    asm volatile("ldmatrix.sync.aligned.m8n8.x4.trans.shared.b16 {%0,%1,%2,%3}, [%4];"
                 : "=r"(r0), "=r"(r1), "=r"(r2), "=r"(r3) : "r"(a));
}
__device__ __forceinline__ void mma16816(float* c, const uint32_t* a, uint32_t b0, uint32_t b1) {
    asm volatile(
        "mma.sync.aligned.m16n8k16.row.col.f32.f16.f16.f32 "
        "{%0,%1,%2,%3}, {%4,%5,%6,%7}, {%8,%9}, {%0,%1,%2,%3};"
        : "+f"(c[0]), "+f"(c[1]), "+f"(c[2]), "+f"(c[3])
        : "r"(a[0]), "r"(a[1]), "r"(a[2]), "r"(a[3]), "r"(b0), "r"(b1));
}
__device__ __forceinline__ void cpa16(uint32_t dst, const void* src) {
    asm volatile("cp.async.cg.shared.global [%0], [%1], 16;" :: "r"(dst), "l"(src));
}
#define CPA_COMMIT() asm volatile("cp.async.commit_group;" ::: "memory")
#define CPA_WAIT0()  asm volatile("cp.async.wait_group 0;" ::: "memory")

// ---------------- prepass: f32 K/V -> fp16 scratch ----------------
__global__ void __launch_bounds__(256)
kv_half_kernel(const float* __restrict__ k, const float* __restrict__ v)
{
    size_t i = (size_t)blockIdx.x * 256 + threadIdx.x;   // one float4 per matrix
    float4 kv = ((const float4*)k)[i];
    uint32_t h01, h23;
    packh2(kv.x, kv.y, h01);
    packh2(kv.z, kv.w, h23);
    ((uint2*)g_kh)[i] = make_uint2(h01, h23);
    float4 vv = ((const float4*)v)[i];
    packh2(vv.x, vv.y, h01);
    packh2(vv.z, vv.w, h23);
    ((uint2*)g_vh)[i] = make_uint2(h01, h23);
}

// ---------------- main attention kernel ----------------
__global__ void __launch_bounds__(NTH, 2)
attn_mma_kernel(const float* __restrict__ q, float* __restrict__ out,
                float* __restrict__ attn)
{
    extern __shared__ char smem[];
    const uint32_t sb = s2u(smem);
    const int tid = threadIdx.x;
    const int w = tid >> 5, lane = tid & 31;
    const int wr = w >> 1;       // row block (16 rows)
    const int wc = w & 1;        // key-half (32 keys)
    const int quad = lane >> 2, qlane = lane & 3;
    const int qt = blockIdx.x, b = blockIdx.y;
    const int qbase = qt * TQ;

    // ---- load Q tile -> fp16 smem ----
    {
        const float* qg = q + ((size_t)(b * SS + qbase)) * DDIM;
        #pragma unroll
        for (int it = 0; it < 4; ++it) {
            int idx = tid + it * NTH;
            int row = idx >> 4, d4 = (idx & 15) << 2;
            float4 qv = *(const float4*)(qg + row * DDIM + d4);
            uint32_t h01, h23;
            packh2(qv.x, qv.y, h01);
            packh2(qv.z, qv.w, h23);
            *(uint2*)(smem + OQHI + row * RS + d4 * 2) = make_uint2(h01, h23);
        }
    }

    // ---- prefetch fp16 K/V tile 0 into buffer 0 ----
    {
        const uint32_t* kh = g_kh + ((size_t)b * SS) * (DDIM / 2);
        const uint32_t* vh = g_vh + ((size_t)b * SS) * (DDIM / 2);
        #pragma unroll
        for (int it = 0; it < 2; ++it) {
            int idx = tid + it * NTH;          // 0..511 : 16B chunks
            int row = idx >> 3, ch = idx & 7;
            cpa16(sb + OK0 + row * RS + ch * 16, kh + row * 32 + ch * 4);
            cpa16(sb + OV0 + row * RS + ch * 16, vh + row * 32 + ch * 4);
        }
        CPA_COMMIT();
    }
    __syncthreads();

    // ---- Q fragments (registers, whole CTA lifetime) ----
    uint32_t qh[4][4];
    {
        uint32_t arow = (uint32_t)(wr * 16 + (lane & 15)) * RS + (uint32_t)(lane >> 4) * 16;
        #pragma unroll
        for (int ks = 0; ks < 4; ++ks)
            ldm4(qh[ks][0], qh[ks][1], qh[ks][2], qh[ks][3], sb + OQHI + arow + ks * 32);
    }

    float O[8][4];
    #pragma unroll
    for (int j = 0; j < 8; ++j)
        #pragma unroll
        for (int i = 0; i < 4; ++i) O[j][i] = 0.f;
    float lsum0 = 0.f, lsum1 = 0.f;
    const float CEXP = 0.18033688011112042f;  // (1/8)*log2(e)

    // lane-relative base offsets (buffer base added per tile)
    const uint32_t koff = (uint32_t)(wc * 32 + ((lane >> 4) << 3) + (lane & 7)) * RS
                        + (uint32_t)((lane >> 3) & 1) * 16;
    const uint32_t voff = (uint32_t)(wc * 32 + (((lane >> 3) & 1) << 3) + (lane & 7)) * RS
                        + (uint32_t)(lane >> 4) * 16;

    float* arow0 = attn + ((size_t)(b * SS + qbase + wr * 16 + quad)) * SS + wc * 32 + 2 * qlane;
    float* arow1 = arow0 + 8 * (size_t)SS;

    for (int kt = 0; kt < NKT; ++kt) {
        const int kbase = kt * TK;
        CPA_WAIT0();
        __syncthreads();   // tile(kt) data visible; all compute of kt-1 done

        const uint32_t kb = sb + ((kt & 1) ? OK1 : OK0);
        const uint32_t vb = sb + ((kt & 1) ? OV1 : OV0);

        // ---- prefetch next fp16 tile into the other buffer (overlaps MMA) ----
        if (kt + 1 < NKT) {
            const uint32_t obK = (kt & 1) ? OK0 : OK1;
            const uint32_t obV = (kt & 1) ? OV0 : OV1;
            const uint32_t* kh = g_kh + ((size_t)(b * SS + kbase + TK)) * (DDIM / 2);
            const uint32_t* vh = g_vh + ((size_t)(b * SS + kbase + TK)) * (DDIM / 2);
            #pragma unroll
            for (int it = 0; it < 2; ++it) {
                int idx = tid + it * NTH;
                int row = idx >> 3, ch = idx & 7;
                cpa16(sb + obK + row * RS + ch * 16, kh + row * 32 + ch * 4);
                cpa16(sb + obV + row * RS + ch * 16, vh + row * 32 + ch * 4);
            }
            CPA_COMMIT();
        }

        // ---- S = QK^T, single-term fp16, ldmatrix pipelined ----
        float c[4][4];
        #pragma unroll
        for (int j = 0; j < 4; ++j)
            #pragma unroll
            for (int i = 0; i < 4; ++i) c[j][i] = 0.f;

        {
            uint32_t cbh[4], pbh[4];
            ldm4(cbh[0], cbh[1], cbh[2], cbh[3], kb + koff);
            #pragma unroll
            for (int gi = 0; gi < 8; ++gi) {
                int ks = gi >> 1, half = gi & 1;
                if (gi < 7) {
                    int ksn = (gi + 1) >> 1, hn = (gi + 1) & 1;
                    uint32_t offn = (uint32_t)ksn * 32 + (uint32_t)hn * (16 * RS);
                    ldm4(pbh[0], pbh[1], pbh[2], pbh[3], kb + koff + offn);
                }
                int j0 = 2 * half;
                mma16816(c[j0],     qh[ks], cbh[0], cbh[1]);
                mma16816(c[j0 + 1], qh[ks], cbh[2], cbh[3]);
                #pragma unroll
                for (int t = 0; t < 4; ++t) cbh[t] = pbh[t];
            }
        }

        // ---- exp (overwrite c with e), attn STG (unnormalized), row sums ----
        #pragma unroll
        for (int j = 0; j < 4; ++j) {
            #pragma unroll
            for (int i = 0; i < 4; ++i) c[j][i] = exp2f(c[j][i] * CEXP);
            lsum0 += c[j][0] + c[j][1];
            lsum1 += c[j][2] + c[j][3];
            *(float2*)(arow0 + kbase + 8 * j) = make_float2(c[j][0], c[j][1]);
            *(float2*)(arow1 + kbase + 8 * j) = make_float2(c[j][2], c[j][3]);
        }

        // ---- O += P V, single-term fp16 ----
        #pragma unroll
        for (int ks2 = 0; ks2 < 2; ++ks2) {
            int t2 = 2 * ks2;
            uint32_t ah[4];
            packh2(c[t2][0],     c[t2][1],     ah[0]);
            packh2(c[t2][2],     c[t2][3],     ah[1]);
            packh2(c[t2 + 1][0], c[t2 + 1][1], ah[2]);
            packh2(c[t2 + 1][2], c[t2 + 1][3], ah[3]);
            uint32_t va = vb + voff + (uint32_t)ks2 * (16 * RS);
            #pragma unroll
            for (int m = 0; m < 4; ++m) {
                uint32_t bh0, bh1, bh2, bh3;
                ldm4t(bh0, bh1, bh2, bh3, va + m * 32);
                mma16816(O[2 * m],     ah, bh0, bh1);
                mma16816(O[2 * m + 1], ah, bh2, bh3);
            }
        }
    }

    // ---- row-sum reduction across quad lanes ----
    lsum0 += __shfl_xor_sync(0xFFFFFFFFu, lsum0, 1);
    lsum0 += __shfl_xor_sync(0xFFFFFFFFu, lsum0, 2);
    lsum1 += __shfl_xor_sync(0xFFFFFFFFu, lsum1, 1);
    lsum1 += __shfl_xor_sync(0xFFFFFFFFu, lsum1, 2);

    float* lbuf = (float*)(smem + OLBUF);
    float* linv = (float*)(smem + OLINV);
    float* ored = (float*)(smem + ORED);

    __syncthreads();   // main-loop smem reads done before epilogue overwrite
    if (qlane == 0) {
        lbuf[wc * 64 + wr * 16 + quad]     = lsum0;
        lbuf[wc * 64 + wr * 16 + quad + 8] = lsum1;
    }
    if (wc == 1) {
        #pragma unroll
        for (int j = 0; j < 8; ++j) {
            *(float2*)(ored + (wr * 16 + quad) * 68 + 8 * j + 2 * qlane)     = make_float2(O[j][0], O[j][1]);
            *(float2*)(ored + (wr * 16 + quad + 8) * 68 + 8 * j + 2 * qlane) = make_float2(O[j][2], O[j][3]);
        }
    }
    __syncthreads();
    if (tid < 64) {
        float s = lbuf[tid] + lbuf[64 + tid];
        linv[tid] = 1.0f / s;
    }
    __syncthreads();

    // ---- O epilogue: reduce halves, normalize, store ----
    if (wc == 0) {
        int r0 = wr * 16 + quad, r1 = r0 + 8;
        float inv0 = linv[r0], inv1 = linv[r1];
        float* op0 = out + ((size_t)(b * SS + qbase + r0)) * DDIM + 2 * qlane;
        float* op1 = out + ((size_t)(b * SS + qbase + r1)) * DDIM + 2 * qlane;
        #pragma unroll
        for (int j = 0; j < 8; ++j) {
            float2 p01 = *(float2*)(ored + r0 * 68 + 8 * j + 2 * qlane);
            float2 p23 = *(float2*)(ored + r1 * 68 + 8 * j + 2 * qlane);
            *(float2*)(op0 + 8 * j) = make_float2((O[j][0] + p01.x) * inv0, (O[j][1] + p01.y) * inv0);
            *(float2*)(op1 + 8 * j) = make_float2((O[j][2] + p23.x) * inv1, (O[j][3] + p23.y) * inv1);
        }
    }

    // ---- fused attn normalize tail (L2-resident RMW of own rows) ----
    {
        float4* abase = (float4*)(attn + ((size_t)(b * SS + qbase)) * SS);
        #pragma unroll 8
        for (int it = 0; it < 128; ++it) {
            int idx = tid + it * NTH;       // 0..32767 float4s
            int row = idx >> 9;             // 512 float4 per row
            int c4  = idx & 511;
            float inv = linv[row];
            float4* p = abase + (size_t)row * (SS / 4) + c4;
            float4 vv = *p;
            vv.x *= inv; vv.y *= inv; vv.z *= inv; vv.w *= inv;
            *p = vv;
        }
    }
}

extern "C" void kernel_launch(void* const* d_in, const int* in_sizes, int n_in,
                              void* d_out, int out_size)
{
    const float* q = (const float*)d_in[0];
    const float* k = (const float*)d_in[1];
    const float* v = (const float*)d_in[2];
    float* out  = (float*)d_out;
    float* attn = out + (size_t)BB * SS * DDIM;

    // prepass: convert K/V to fp16 scratch
    size_t nf4 = (size_t)BB * SS * DDIM / 4;           // 1,048,576 float4s
    kv_half_kernel<<<(unsigned)(nf4 / 256), 256>>>(k, v);

    cudaFuncSetAttribute(attn_mma_kernel,
                         cudaFuncAttributeMaxDynamicSharedMemorySize, SMEMSZ);

    dim3 grid(SS / TQ, BB);
    attn_mma_kernel<<<grid, NTH, SMEMSZ>>>(q, out, attn);
}

// round 15
// speedup vs baseline: 1.4572x; 1.1818x over previous
#include <cuda_runtime.h>
#include <cstdint>

#define BB 32
#define SS 2048
#define DDIM 64
#define TQ 64
#define TK 64
#define NKT 32
#define NTH 256

// fp16 tile row stride: 72 elems = 144 bytes (16B-aligned, ldmatrix conflict-free)
#define RS 144
// smem byte offsets (double-buffered fp16 K/V)
#define OQHI 0u               // Q tile: 64 x 64 fp16 (9216 B)
#define OK0  9216u
#define OV0  18432u
#define OK1  27648u
#define OV1  36864u
#define SMEMSZ 46080u
// epilogue reduce area reuses Q/K regions (dead after main loop)
#define ORED  0u        // fp32 [64][68] O partials
#define OLBUF 17408u    // fp32 [128] row-sum partials
#define OLINV 17920u    // fp32 [64] inverse row sums

// fp16 K/V scratch (8 MB each) + fp16 unnormalized-e scratch (256 MB)
__device__ uint32_t g_kh[BB * SS * DDIM / 2];
__device__ uint32_t g_vh[BB * SS * DDIM / 2];
__device__ uint32_t g_eh[(size_t)BB * SS * SS / 2];

// ---------------- helpers ----------------
__device__ __forceinline__ uint32_t s2u(const void* p) {
    uint32_t a;
    asm("{ .reg .u64 t; cvta.to.shared.u64 t, %1; cvt.u32.u64 %0, t; }" : "=r"(a) : "l"(p));
    return a;
}
// pack (a,b) -> fp16x2 (a in low half)
__device__ __forceinline__ void packh2(float a, float b, uint32_t& h) {
    asm("cvt.rn.f16x2.f32 %0, %1, %2;" : "=r"(h) : "f"(b), "f"(a));
}
__device__ __forceinline__ void unpackh2(uint32_t h, float& fa, float& fb) {
    asm("{ .reg .b16 x, y; mov.b32 {x, y}, %2; cvt.f32.f16 %0, x; cvt.f32.f16 %1, y; }"
        : "=f"(fa), "=f"(fb) : "r"(h));
}
__device__ __forceinline__ void ldm4(uint32_t& r0, uint32_t& r1, uint32_t& r2, uint32_t& r3, uint32_t a) {
    asm volatile("ldmatrix.sync.aligned.m8n8.x4.shared.b16 {%0,%1,%2,%3}, [%4];"
                 : "=r"(r0), "=r"(r1), "=r"(r2), "=r"(r3) : "r"(a));
}
__device__ __forceinline__ void ldm4t(uint32_t& r0, uint32_t& r1, uint32_t& r2, uint32_t& r3, uint32_t a) {
    asm volatile("ldmatrix.sync.aligned.m8n8.x4.trans.shared.b16 {%0,%1,%2,%3}, [%4];"
                 : "=r"(r0), "=r"(r1), "=r"(r2), "=r"(r3) : "r"(a));
}
__device__ __forceinline__ void mma16816(float* c, const uint32_t* a, uint32_t b0, uint32_t b1) {
    asm volatile(
        "mma.sync.aligned.m16n8k16.row.col.f32.f16.f16.f32 "
        "{%0,%1,%2,%3}, {%4,%5,%6,%7}, {%8,%9}, {%0,%1,%2,%3};"
        : "+f"(c[0]), "+f"(c[1]), "+f"(c[2]), "+f"(c[3])
        : "r"(a[0]), "r"(a[1]), "r"(a[2]), "r"(a[3]), "r"(b0), "r"(b1));
}
__device__ __forceinline__ void cpa16(uint32_t dst, const void* src) {
    asm volatile("cp.async.cg.shared.global [%0], [%1], 16;" :: "r"(dst), "l"(src));
}
#define CPA_COMMIT() asm volatile("cp.async.commit_group;" ::: "memory")
#define CPA_WAIT0()  asm volatile("cp.async.wait_group 0;" ::: "memory")

// ---------------- prepass: f32 K/V -> fp16 scratch ----------------
__global__ void __launch_bounds__(256)
kv_half_kernel(const float* __restrict__ k, const float* __restrict__ v)
{
    size_t i = (size_t)blockIdx.x * 256 + threadIdx.x;   // one float4 per matrix
    float4 kv = ((const float4*)k)[i];
    uint32_t h01, h23;
    packh2(kv.x, kv.y, h01);
    packh2(kv.z, kv.w, h23);
    ((uint2*)g_kh)[i] = make_uint2(h01, h23);
    float4 vv = ((const float4*)v)[i];
    packh2(vv.x, vv.y, h01);
    packh2(vv.z, vv.w, h23);
    ((uint2*)g_vh)[i] = make_uint2(h01, h23);
}

// ---------------- main attention kernel ----------------
__global__ void __launch_bounds__(NTH, 2)
attn_mma_kernel(const float* __restrict__ q, float* __restrict__ out,
                float* __restrict__ attn)
{
    extern __shared__ char smem[];
    const uint32_t sb = s2u(smem);
    const int tid = threadIdx.x;
    const int w = tid >> 5, lane = tid & 31;
    const int wr = w >> 1;       // row block (16 rows)
    const int wc = w & 1;        // key-half (32 keys)
    const int quad = lane >> 2, qlane = lane & 3;
    const int qt = blockIdx.x, b = blockIdx.y;
    const int qbase = qt * TQ;

    // ---- load Q tile -> fp16 smem ----
    {
        const float* qg = q + ((size_t)(b * SS + qbase)) * DDIM;
        #pragma unroll
        for (int it = 0; it < 4; ++it) {
            int idx = tid + it * NTH;
            int row = idx >> 4, d4 = (idx & 15) << 2;
            float4 qv = *(const float4*)(qg + row * DDIM + d4);
            uint32_t h01, h23;
            packh2(qv.x, qv.y, h01);
            packh2(qv.z, qv.w, h23);
            *(uint2*)(smem + OQHI + row * RS + d4 * 2) = make_uint2(h01, h23);
        }
    }

    // ---- prefetch fp16 K/V tile 0 into buffer 0 ----
    {
        const uint32_t* kh = g_kh + ((size_t)b * SS) * (DDIM / 2);
        const uint32_t* vh = g_vh + ((size_t)b * SS) * (DDIM / 2);
        #pragma unroll
        for (int it = 0; it < 2; ++it) {
            int idx = tid + it * NTH;          // 0..511 : 16B chunks
            int row = idx >> 3, ch = idx & 7;
            cpa16(sb + OK0 + row * RS + ch * 16, kh + row * 32 + ch * 4);
            cpa16(sb + OV0 + row * RS + ch * 16, vh + row * 32 + ch * 4);
        }
        CPA_COMMIT();
    }
    __syncthreads();

    // ---- Q fragments (registers, whole CTA lifetime) ----
    uint32_t qh[4][4];
    {
        uint32_t arow = (uint32_t)(wr * 16 + (lane & 15)) * RS + (uint32_t)(lane >> 4) * 16;
        #pragma unroll
        for (int ks = 0; ks < 4; ++ks)
            ldm4(qh[ks][0], qh[ks][1], qh[ks][2], qh[ks][3], sb + OQHI + arow + ks * 32);
    }

    float O[8][4];
    #pragma unroll
    for (int j = 0; j < 8; ++j)
        #pragma unroll
        for (int i = 0; i < 4; ++i) O[j][i] = 0.f;
    float lsum0 = 0.f, lsum1 = 0.f;
    const float CEXP = 0.18033688011112042f;  // (1/8)*log2(e)

    // lane-relative base offsets (buffer base added per tile)
    const uint32_t koff = (uint32_t)(wc * 32 + ((lane >> 4) << 3) + (lane & 7)) * RS
                        + (uint32_t)((lane >> 3) & 1) * 16;
    const uint32_t voff = (uint32_t)(wc * 32 + (((lane >> 3) & 1) << 3) + (lane & 7)) * RS
                        + (uint32_t)(lane >> 4) * 16;

    // fp16 e scratch row pointers (uint32 = 2 packed cols)
    uint32_t* erow0 = g_eh + ((size_t)(b * SS + qbase + wr * 16 + quad)) * (SS / 2)
                    + wc * 16 + qlane;
    uint32_t* erow1 = erow0 + 8 * (size_t)(SS / 2);

    for (int kt = 0; kt < NKT; ++kt) {
        const int kbase = kt * TK;
        CPA_WAIT0();
        __syncthreads();   // tile(kt) data visible; all compute of kt-1 done

        const uint32_t kb = sb + ((kt & 1) ? OK1 : OK0);
        const uint32_t vb = sb + ((kt & 1) ? OV1 : OV0);

        // ---- prefetch next fp16 tile into the other buffer (overlaps MMA) ----
        if (kt + 1 < NKT) {
            const uint32_t obK = (kt & 1) ? OK0 : OK1;
            const uint32_t obV = (kt & 1) ? OV0 : OV1;
            const uint32_t* kh = g_kh + ((size_t)(b * SS + kbase + TK)) * (DDIM / 2);
            const uint32_t* vh = g_vh + ((size_t)(b * SS + kbase + TK)) * (DDIM / 2);
            #pragma unroll
            for (int it = 0; it < 2; ++it) {
                int idx = tid + it * NTH;
                int row = idx >> 3, ch = idx & 7;
                cpa16(sb + obK + row * RS + ch * 16, kh + row * 32 + ch * 4);
                cpa16(sb + obV + row * RS + ch * 16, vh + row * 32 + ch * 4);
            }
            CPA_COMMIT();
        }

        // ---- S = QK^T, single-term fp16, ldmatrix pipelined ----
        float c[4][4];
        #pragma unroll
        for (int j = 0; j < 4; ++j)
            #pragma unroll
            for (int i = 0; i < 4; ++i) c[j][i] = 0.f;

        {
            uint32_t cbh[4], pbh[4];
            ldm4(cbh[0], cbh[1], cbh[2], cbh[3], kb + koff);
            #pragma unroll
            for (int gi = 0; gi < 8; ++gi) {
                int ks = gi >> 1, half = gi & 1;
                if (gi < 7) {
                    int ksn = (gi + 1) >> 1, hn = (gi + 1) & 1;
                    uint32_t offn = (uint32_t)ksn * 32 + (uint32_t)hn * (16 * RS);
                    ldm4(pbh[0], pbh[1], pbh[2], pbh[3], kb + koff + offn);
                }
                int j0 = 2 * half;
                mma16816(c[j0],     qh[ks], cbh[0], cbh[1]);
                mma16816(c[j0 + 1], qh[ks], cbh[2], cbh[3]);
                #pragma unroll
                for (int t = 0; t < 4; ++t) cbh[t] = pbh[t];
            }
        }

        // ---- exp, pack fp16 pairs (shared with PV), store e scratch, sums ----
        uint32_t ah[8];
        #pragma unroll
        for (int j = 0; j < 4; ++j) {
            #pragma unroll
            for (int i = 0; i < 4; ++i) c[j][i] = exp2f(c[j][i] * CEXP);
            lsum0 += c[j][0] + c[j][1];
            lsum1 += c[j][2] + c[j][3];
            packh2(c[j][0], c[j][1], ah[2 * j]);
            packh2(c[j][2], c[j][3], ah[2 * j + 1]);
            erow0[(kbase >> 1) + 4 * j] = ah[2 * j];
            erow1[(kbase >> 1) + 4 * j] = ah[2 * j + 1];
        }

        // ---- O += P V, single-term fp16 (A-frags reuse packed e) ----
        #pragma unroll
        for (int ks2 = 0; ks2 < 2; ++ks2) {
            uint32_t va = vb + voff + (uint32_t)ks2 * (16 * RS);
            #pragma unroll
            for (int m = 0; m < 4; ++m) {
                uint32_t bh0, bh1, bh2, bh3;
                ldm4t(bh0, bh1, bh2, bh3, va + m * 32);
                mma16816(O[2 * m],     &ah[4 * ks2], bh0, bh1);
                mma16816(O[2 * m + 1], &ah[4 * ks2], bh2, bh3);
            }
        }
    }

    // ---- row-sum reduction across quad lanes ----
    lsum0 += __shfl_xor_sync(0xFFFFFFFFu, lsum0, 1);
    lsum0 += __shfl_xor_sync(0xFFFFFFFFu, lsum0, 2);
    lsum1 += __shfl_xor_sync(0xFFFFFFFFu, lsum1, 1);
    lsum1 += __shfl_xor_sync(0xFFFFFFFFu, lsum1, 2);

    float* lbuf = (float*)(smem + OLBUF);
    float* linv = (float*)(smem + OLINV);
    float* ored = (float*)(smem + ORED);

    __syncthreads();   // main-loop smem reads done before epilogue overwrite
    if (qlane == 0) {
        lbuf[wc * 64 + wr * 16 + quad]     = lsum0;
        lbuf[wc * 64 + wr * 16 + quad + 8] = lsum1;
    }
    if (wc == 1) {
        #pragma unroll
        for (int j = 0; j < 8; ++j) {
            *(float2*)(ored + (wr * 16 + quad) * 68 + 8 * j + 2 * qlane)     = make_float2(O[j][0], O[j][1]);
            *(float2*)(ored + (wr * 16 + quad + 8) * 68 + 8 * j + 2 * qlane) = make_float2(O[j][2], O[j][3]);
        }
    }
    __syncthreads();
    if (tid < 64) {
        float s = lbuf[tid] + lbuf[64 + tid];
        linv[tid] = 1.0f / s;
    }
    __syncthreads();

    // ---- O epilogue: reduce halves, normalize, store ----
    if (wc == 0) {
        int r0 = wr * 16 + quad, r1 = r0 + 8;
        float inv0 = linv[r0], inv1 = linv[r1];
        float* op0 = out + ((size_t)(b * SS + qbase + r0)) * DDIM + 2 * qlane;
        float* op1 = out + ((size_t)(b * SS + qbase + r1)) * DDIM + 2 * qlane;
        #pragma unroll
        for (int j = 0; j < 8; ++j) {
            float2 p01 = *(float2*)(ored + r0 * 68 + 8 * j + 2 * qlane);
            float2 p23 = *(float2*)(ored + r1 * 68 + 8 * j + 2 * qlane);
            *(float2*)(op0 + 8 * j) = make_float2((O[j][0] + p01.x) * inv0, (O[j][1] + p01.y) * inv0);
            *(float2*)(op1 + 8 * j) = make_float2((O[j][2] + p23.x) * inv1, (O[j][3] + p23.y) * inv1);
        }
    }

    // ---- attn tail: read fp16 e scratch (L2-hot), write normalized fp32 ----
    {
        const uint32_t* ebase = g_eh + ((size_t)(b * SS + qbase)) * (SS / 2);
        float* abase = attn + ((size_t)(b * SS + qbase)) * SS;
        #pragma unroll 4
        for (int it = 0; it < 64; ++it) {
            int idx = tid + it * NTH;       // 0..16383 uint4 chunks (8 cols each)
            int row = idx >> 8;             // 256 chunks per row
            int c8  = idx & 255;
            float inv = linv[row];
            uint4 pk = *(const uint4*)(ebase + (size_t)row * (SS / 2) + c8 * 4);
            float f0, f1, f2, f3, f4, f5, f6, f7;
            unpackh2(pk.x, f0, f1);
            unpackh2(pk.y, f2, f3);
            unpackh2(pk.z, f4, f5);
            unpackh2(pk.w, f6, f7);
            float4* p = (float4*)(abase + (size_t)row * SS + c8 * 8);
            __stcs(p,     make_float4(f0 * inv, f1 * inv, f2 * inv, f3 * inv));
            __stcs(p + 1, make_float4(f4 * inv, f5 * inv, f6 * inv, f7 * inv));
        }
    }
}

extern "C" void kernel_launch(void* const* d_in, const int* in_sizes, int n_in,
                              void* d_out, int out_size)
{
    const float* q = (const float*)d_in[0];
    const float* k = (const float*)d_in[1];
    const float* v = (const float*)d_in[2];
    float* out  = (float*)d_out;
    float* attn = out + (size_t)BB * SS * DDIM;

    // prepass: convert K/V to fp16 scratch
    size_t nf4 = (size_t)BB * SS * DDIM / 4;           // 1,048,576 float4s
    kv_half_kernel<<<(unsigned)(nf4 / 256), 256>>>(k, v);

    cudaFuncSetAttribute(attn_mma_kernel,
                         cudaFuncAttributeMaxDynamicSharedMemorySize, SMEMSZ);

    dim3 grid(SS / TQ, BB);
    attn_mma_kernel<<<grid, NTH, SMEMSZ>>>(q, out, attn);
}

// round 16
// speedup vs baseline: 1.4671x; 1.0068x over previous
#include <cuda_runtime.h>
#include <cstdint>

#define BB 32
#define SS 2048
#define DDIM 64
#define TQ 64
#define TK 64
#define NKT 32
#define NTH 256

// fp16 tile row stride: 72 elems = 144 bytes (16B-aligned, ldmatrix conflict-free)
#define RS 144
// smem byte offsets (double-buffered fp16 K/V)
#define OQHI 0u               // Q tile: 64 x 64 fp16 (9216 B)
#define OK0  9216u
#define OV0  18432u
#define OK1  27648u
#define OV1  36864u
#define SMEMSZ 46080u
// epilogue reduce area reuses Q/K regions (dead after main loop)
#define ORED  0u        // fp32 [64][68] O partials
#define OLBUF 17408u    // fp32 [128] row-sum partials
#define OLINV 17920u    // fp32 [64] inverse row sums

// fp16 K/V scratch (8 MB each) + fp16 unnormalized-e scratch (256 MB)
__device__ uint32_t g_kh[BB * SS * DDIM / 2];
__device__ uint32_t g_vh[BB * SS * DDIM / 2];
__device__ uint32_t g_eh[(size_t)BB * SS * SS / 2];

// ---------------- helpers ----------------
__device__ __forceinline__ uint32_t s2u(const void* p) {
    uint32_t a;
    asm("{ .reg .u64 t; cvta.to.shared.u64 t, %1; cvt.u32.u64 %0, t; }" : "=r"(a) : "l"(p));
    return a;
}
// pack (a,b) -> fp16x2 (a in low half)
__device__ __forceinline__ void packh2(float a, float b, uint32_t& h) {
    asm("cvt.rn.f16x2.f32 %0, %1, %2;" : "=r"(h) : "f"(b), "f"(a));
}
__device__ __forceinline__ void unpackh2(uint32_t h, float& fa, float& fb) {
    asm("{ .reg .b16 x, y; mov.b32 {x, y}, %2; cvt.f32.f16 %0, x; cvt.f32.f16 %1, y; }"
        : "=f"(fa), "=f"(fb) : "r"(h));
}
// single-instruction exp2 approx (MUFU.EX2)
__device__ __forceinline__ float ex2(float x) {
    float r;
    asm("ex2.approx.ftz.f32 %0, %1;" : "=f"(r) : "f"(x));
    return r;
}
__device__ __forceinline__ void ldm4(uint32_t& r0, uint32_t& r1, uint32_t& r2, uint32_t& r3, uint32_t a) {
    asm volatile("ldmatrix.sync.aligned.m8n8.x4.shared.b16 {%0,%1,%2,%3}, [%4];"
                 : "=r"(r0), "=r"(r1), "=r"(r2), "=r"(r3) : "r"(a));
}
__device__ __forceinline__ void ldm4t(uint32_t& r0, uint32_t& r1, uint32_t& r2, uint32_t& r3, uint32_t a) {
    asm volatile("ldmatrix.sync.aligned.m8n8.x4.trans.shared.b16 {%0,%1,%2,%3}, [%4];"
                 : "=r"(r0), "=r"(r1), "=r"(r2), "=r"(r3) : "r"(a));
}
__device__ __forceinline__ void mma16816(float* c, const uint32_t* a, uint32_t b0, uint32_t b1) {
    asm volatile(
        "mma.sync.aligned.m16n8k16.row.col.f32.f16.f16.f32 "
        "{%0,%1,%2,%3}, {%4,%5,%6,%7}, {%8,%9}, {%0,%1,%2,%3};"
        : "+f"(c[0]), "+f"(c[1]), "+f"(c[2]), "+f"(c[3])
        : "r"(a[0]), "r"(a[1]), "r"(a[2]), "r"(a[3]), "r"(b0), "r"(b1));
}
__device__ __forceinline__ void cpa16(uint32_t dst, const void* src) {
    asm volatile("cp.async.cg.shared.global [%0], [%1], 16;" :: "r"(dst), "l"(src));
}
#define CPA_COMMIT() asm volatile("cp.async.commit_group;" ::: "memory")
#define CPA_WAIT0()  asm volatile("cp.async.wait_group 0;" ::: "memory")

// ---------------- prepass: f32 K/V -> fp16 scratch ----------------
__global__ void __launch_bounds__(256)
kv_half_kernel(const float* __restrict__ k, const float* __restrict__ v)
{
    size_t i = (size_t)blockIdx.x * 256 + threadIdx.x;   // one float4 per matrix
    float4 kv = ((const float4*)k)[i];
    uint32_t h01, h23;
    packh2(kv.x, kv.y, h01);
    packh2(kv.z, kv.w, h23);
    ((uint2*)g_kh)[i] = make_uint2(h01, h23);
    float4 vv = ((const float4*)v)[i];
    packh2(vv.x, vv.y, h01);
    packh2(vv.z, vv.w, h23);
    ((uint2*)g_vh)[i] = make_uint2(h01, h23);
}

// ---------------- main attention kernel ----------------
__global__ void __launch_bounds__(NTH, 2)
attn_mma_kernel(const float* __restrict__ q, float* __restrict__ out,
                float* __restrict__ attn)
{
    extern __shared__ char smem[];
    const uint32_t sb = s2u(smem);
    const int tid = threadIdx.x;
    const int w = tid >> 5, lane = tid & 31;
    const int wr = w >> 1;       // row block (16 rows)
    const int wc = w & 1;        // key-half (32 keys)
    const int quad = lane >> 2, qlane = lane & 3;
    const int qt = blockIdx.x, b = blockIdx.y;
    const int qbase = qt * TQ;

    const float CEXP = 0.18033688011112042f;  // (1/8)*log2(e), folded into Q

    // ---- load Q tile (pre-scaled by CEXP) -> fp16 smem ----
    {
        const float* qg = q + ((size_t)(b * SS + qbase)) * DDIM;
        #pragma unroll
        for (int it = 0; it < 4; ++it) {
            int idx = tid + it * NTH;
            int row = idx >> 4, d4 = (idx & 15) << 2;
            float4 qv = *(const float4*)(qg + row * DDIM + d4);
            uint32_t h01, h23;
            packh2(qv.x * CEXP, qv.y * CEXP, h01);
            packh2(qv.z * CEXP, qv.w * CEXP, h23);
            *(uint2*)(smem + OQHI + row * RS + d4 * 2) = make_uint2(h01, h23);
        }
    }

    // ---- prefetch fp16 K/V tile 0 into buffer 0 ----
    {
        const uint32_t* kh = g_kh + ((size_t)b * SS) * (DDIM / 2);
        const uint32_t* vh = g_vh + ((size_t)b * SS) * (DDIM / 2);
        #pragma unroll
        for (int it = 0; it < 2; ++it) {
            int idx = tid + it * NTH;          // 0..511 : 16B chunks
            int row = idx >> 3, ch = idx & 7;
            cpa16(sb + OK0 + row * RS + ch * 16, kh + row * 32 + ch * 4);
            cpa16(sb + OV0 + row * RS + ch * 16, vh + row * 32 + ch * 4);
        }
        CPA_COMMIT();
    }
    __syncthreads();

    // ---- Q fragments (registers, whole CTA lifetime) ----
    uint32_t qh[4][4];
    {
        uint32_t arow = (uint32_t)(wr * 16 + (lane & 15)) * RS + (uint32_t)(lane >> 4) * 16;
        #pragma unroll
        for (int ks = 0; ks < 4; ++ks)
            ldm4(qh[ks][0], qh[ks][1], qh[ks][2], qh[ks][3], sb + OQHI + arow + ks * 32);
    }

    float O[8][4];
    #pragma unroll
    for (int j = 0; j < 8; ++j)
        #pragma unroll
        for (int i = 0; i < 4; ++i) O[j][i] = 0.f;
    float lsum0 = 0.f, lsum1 = 0.f;

    // lane-relative base offsets (buffer base added per tile)
    const uint32_t koff = (uint32_t)(wc * 32 + ((lane >> 4) << 3) + (lane & 7)) * RS
                        + (uint32_t)((lane >> 3) & 1) * 16;
    const uint32_t voff = (uint32_t)(wc * 32 + (((lane >> 3) & 1) << 3) + (lane & 7)) * RS
                        + (uint32_t)(lane >> 4) * 16;

    // fp16 e scratch row pointers (uint32 = 2 packed cols)
    uint32_t* erow0 = g_eh + ((size_t)(b * SS + qbase + wr * 16 + quad)) * (SS / 2)
                    + wc * 16 + qlane;
    uint32_t* erow1 = erow0 + 8 * (size_t)(SS / 2);

    for (int kt = 0; kt < NKT; ++kt) {
        const int kbase = kt * TK;
        CPA_WAIT0();
        __syncthreads();   // tile(kt) data visible; all compute of kt-1 done

        const uint32_t kb = sb + ((kt & 1) ? OK1 : OK0);
        const uint32_t vb = sb + ((kt & 1) ? OV1 : OV0);

        // ---- prefetch next fp16 tile into the other buffer (overlaps MMA) ----
        if (kt + 1 < NKT) {
            const uint32_t obK = (kt & 1) ? OK0 : OK1;
            const uint32_t obV = (kt & 1) ? OV0 : OV1;
            const uint32_t* kh = g_kh + ((size_t)(b * SS + kbase + TK)) * (DDIM / 2);
            const uint32_t* vh = g_vh + ((size_t)(b * SS + kbase + TK)) * (DDIM / 2);
            #pragma unroll
            for (int it = 0; it < 2; ++it) {
                int idx = tid + it * NTH;
                int row = idx >> 3, ch = idx & 7;
                cpa16(sb + obK + row * RS + ch * 16, kh + row * 32 + ch * 4);
                cpa16(sb + obV + row * RS + ch * 16, vh + row * 32 + ch * 4);
            }
            CPA_COMMIT();
        }

        // ---- S = QK^T, single-term fp16, ldmatrix pipelined ----
        float c[4][4];
        #pragma unroll
        for (int j = 0; j < 4; ++j)
            #pragma unroll
            for (int i = 0; i < 4; ++i) c[j][i] = 0.f;

        {
            uint32_t cbh[4], pbh[4];
            ldm4(cbh[0], cbh[1], cbh[2], cbh[3], kb + koff);
            #pragma unroll
            for (int gi = 0; gi < 8; ++gi) {
                int ks = gi >> 1, half = gi & 1;
                if (gi < 7) {
                    int ksn = (gi + 1) >> 1, hn = (gi + 1) & 1;
                    uint32_t offn = (uint32_t)ksn * 32 + (uint32_t)hn * (16 * RS);
                    ldm4(pbh[0], pbh[1], pbh[2], pbh[3], kb + koff + offn);
                }
                int j0 = 2 * half;
                mma16816(c[j0],     qh[ks], cbh[0], cbh[1]);
                mma16816(c[j0 + 1], qh[ks], cbh[2], cbh[3]);
                #pragma unroll
                for (int t = 0; t < 4; ++t) cbh[t] = pbh[t];
            }
        }

        // ---- exp (single MUFU each; scale pre-folded into Q), pack, sums ----
        uint32_t ah[8];
        #pragma unroll
        for (int j = 0; j < 4; ++j) {
            #pragma unroll
            for (int i = 0; i < 4; ++i) c[j][i] = ex2(c[j][i]);
            lsum0 += c[j][0] + c[j][1];
            lsum1 += c[j][2] + c[j][3];
            packh2(c[j][0], c[j][1], ah[2 * j]);
            packh2(c[j][2], c[j][3], ah[2 * j + 1]);
        }

        // ---- O += P V, single-term fp16, ldmatrix.trans pipelined ----
        {
            uint32_t cv[4], pv[4];
            ldm4t(cv[0], cv[1], cv[2], cv[3], vb + voff);
            #pragma unroll
            for (int g = 0; g < 8; ++g) {
                int ks2 = g >> 2, m = g & 3;
                if (g < 7) {
                    int gn = g + 1;
                    uint32_t offn = (uint32_t)(gn >> 2) * (16 * RS) + (uint32_t)(gn & 3) * 32;
                    ldm4t(pv[0], pv[1], pv[2], pv[3], vb + voff + offn);
                }
                mma16816(O[2 * m],     &ah[4 * ks2], cv[0], cv[1]);
                mma16816(O[2 * m + 1], &ah[4 * ks2], cv[2], cv[3]);
                #pragma unroll
                for (int t = 0; t < 4; ++t) cv[t] = pv[t];
            }
        }

        // ---- e-scratch stores (fire-and-forget, after the MMA chain) ----
        #pragma unroll
        for (int j = 0; j < 4; ++j) {
            erow0[(kbase >> 1) + 4 * j] = ah[2 * j];
            erow1[(kbase >> 1) + 4 * j] = ah[2 * j + 1];
        }
    }

    // ---- row-sum reduction across quad lanes ----
    lsum0 += __shfl_xor_sync(0xFFFFFFFFu, lsum0, 1);
    lsum0 += __shfl_xor_sync(0xFFFFFFFFu, lsum0, 2);
    lsum1 += __shfl_xor_sync(0xFFFFFFFFu, lsum1, 1);
    lsum1 += __shfl_xor_sync(0xFFFFFFFFu, lsum1, 2);

    float* lbuf = (float*)(smem + OLBUF);
    float* linv = (float*)(smem + OLINV);
    float* ored = (float*)(smem + ORED);

    __syncthreads();   // main-loop smem reads done before epilogue overwrite
    if (qlane == 0) {
        lbuf[wc * 64 + wr * 16 + quad]     = lsum0;
        lbuf[wc * 64 + wr * 16 + quad + 8] = lsum1;
    }
    if (wc == 1) {
        #pragma unroll
        for (int j = 0; j < 8; ++j) {
            *(float2*)(ored + (wr * 16 + quad) * 68 + 8 * j + 2 * qlane)     = make_float2(O[j][0], O[j][1]);
            *(float2*)(ored + (wr * 16 + quad + 8) * 68 + 8 * j + 2 * qlane) = make_float2(O[j][2], O[j][3]);
        }
    }
    __syncthreads();
    if (tid < 64) {
        float s = lbuf[tid] + lbuf[64 + tid];
        linv[tid] = 1.0f / s;
    }
    __syncthreads();

    // ---- O epilogue: reduce halves, normalize, store ----
    if (wc == 0) {
        int r0 = wr * 16 + quad, r1 = r0 + 8;
        float inv0 = linv[r0], inv1 = linv[r1];
        float* op0 = out + ((size_t)(b * SS + qbase + r0)) * DDIM + 2 * qlane;
        float* op1 = out + ((size_t)(b * SS + qbase + r1)) * DDIM + 2 * qlane;
        #pragma unroll
        for (int j = 0; j < 8; ++j) {
            float2 p01 = *(float2*)(ored + r0 * 68 + 8 * j + 2 * qlane);
            float2 p23 = *(float2*)(ored + r1 * 68 + 8 * j + 2 * qlane);
            *(float2*)(op0 + 8 * j) = make_float2((O[j][0] + p01.x) * inv0, (O[j][1] + p01.y) * inv0);
            *(float2*)(op1 + 8 * j) = make_float2((O[j][2] + p23.x) * inv1, (O[j][3] + p23.y) * inv1);
        }
    }

    // ---- attn tail: read fp16 e scratch (L2-hot), write normalized fp32 ----
    {
        const uint32_t* ebase = g_eh + ((size_t)(b * SS + qbase)) * (SS / 2);
        float* abase = attn + ((size_t)(b * SS + qbase)) * SS;
        #pragma unroll 4
        for (int it = 0; it < 64; ++it) {
            int idx = tid + it * NTH;       // 0..16383 uint4 chunks (8 cols each)
            int row = idx >> 8;             // 256 chunks per row
            int c8  = idx & 255;
            float inv = linv[row];
            uint4 pk = *(const uint4*)(ebase + (size_t)row * (SS / 2) + c8 * 4);
            float f0, f1, f2, f3, f4, f5, f6, f7;
            unpackh2(pk.x, f0, f1);
            unpackh2(pk.y, f2, f3);
            unpackh2(pk.z, f4, f5);
            unpackh2(pk.w, f6, f7);
            float4* p = (float4*)(abase + (size_t)row * SS + c8 * 8);
            __stcs(p,     make_float4(f0 * inv, f1 * inv, f2 * inv, f3 * inv));
            __stcs(p + 1, make_float4(f4 * inv, f5 * inv, f6 * inv, f7 * inv));
        }
    }
}

extern "C" void kernel_launch(void* const* d_in, const int* in_sizes, int n_in,
                              void* d_out, int out_size)
{
    const float* q = (const float*)d_in[0];
    const float* k = (const float*)d_in[1];
    const float* v = (const float*)d_in[2];
    float* out  = (float*)d_out;
    float* attn = out + (size_t)BB * SS * DDIM;

    // prepass: convert K/V to fp16 scratch
    size_t nf4 = (size_t)BB * SS * DDIM / 4;           // 1,048,576 float4s
    kv_half_kernel<<<(unsigned)(nf4 / 256), 256>>>(k, v);

    cudaFuncSetAttribute(attn_mma_kernel,
                         cudaFuncAttributeMaxDynamicSharedMemorySize, SMEMSZ);

    dim3 grid(SS / TQ, BB);
    attn_mma_kernel<<<grid, NTH, SMEMSZ>>>(q, out, attn);
}